// round 5
// baseline (speedup 1.0000x reference)
#include <cuda_runtime.h>

// B-spline layer, single fused quasi-persistent kernel.
// Per interval ii = floor(55x), out = ((q3*u+q2)*u+q1)*u+q0 with u = 55x-ii,
// where q_d[ii,f] = sum_r P[ii][r][d]*C[ii+3+r,f] (+bias into q0).
// P = Cox-de Boor basis polynomial coefficients in local coord u, computed on
// the HOST in double (knot-only, deterministic), passed in the const bank.
//
// Grid (37,8) = 296 blocks = exactly 2 per SM (one wave). Each block folds its
// 28 KB coefficient tile once, then streams ~110 batch rows.

#define NF 256
#define NBATCH 4096
#define NII 55
#define NK 64
#define NBX 37
#define NTHREADS 512

struct PTab { float p[NII][4][4]; };

// ---------------- host-side knot/coefficient math (double) ----------------
static double knotD_h(int idx) {
    if (idx < 6)  return -0.002 + 0.0005 * (double)(idx - 3);
    if (idx > 61) return 1.001  + 0.0005 * (double)(idx - 62);
    return (double)(idx - 6) / 55.0;
}

static void make_ptab(PTab& T) {
    for (int ii = 0; ii < NII; ++ii) {
        const int j = ii + 6;
        double P[4][4] = {};
        P[0][0] = 1.0;
        const double x0 = (double)ii / 55.0;
        const double bs = 1.0 / 55.0;   // x = x0 + bs*u
        for (int k = 1; k <= 3; ++k) {
            double Q[4][4] = {};
            for (int r = 0; r <= k; ++r) {
                const int i = j - k + r;
                if (r >= 1) {
                    const double inv = 1.0 / (knotD_h(i + k) - knotD_h(i));
                    const double a = (x0 - knotD_h(i)) * inv;
                    const double b = bs * inv;
                    for (int d = 0; d < 4; ++d) {
                        Q[r][d] += a * P[r - 1][d];
                        if (d > 0) Q[r][d] += b * P[r - 1][d - 1];
                    }
                }
                if (r <= k - 1) {
                    const double inv = 1.0 / (knotD_h(i + k + 1) - knotD_h(i + 1));
                    const double a = (knotD_h(i + k + 1) - x0) * inv;
                    const double b = -bs * inv;
                    for (int d = 0; d < 4; ++d) {
                        Q[r][d] += a * P[r][d];
                        if (d > 0) Q[r][d] += b * P[r][d - 1];
                    }
                }
            }
            for (int r = 0; r < 4; ++r)
                for (int d = 0; d < 4; ++d) P[r][d] = Q[r][d];
        }
        for (int r = 0; r < 4; ++r)
            for (int d = 0; d < 4; ++d) T.p[ii][r][d] = (float)P[r][d];
    }
}

// --------------------------------- kernel ---------------------------------
__global__ __launch_bounds__(NTHREADS) void BSL_25898652795515_kernel(
    const PTab T,                     // 3.5 KB const bank
    const float* __restrict__ X,      // (4096, 256)
    const float* __restrict__ C,      // (64, 256)
    const float* __restrict__ bias,   // (256,)
    float* __restrict__ out)          // (4096, 256)
{
    __shared__ float  sC[NK * 32];    // 8 KB control tile
    __shared__ float4 sT[NII * 32];   // 28 KB folded coefficient tile

    const int tile = blockIdx.y;
    const int f0   = tile * 32;
    const int bx   = blockIdx.x;      // 0..36
    const int tid  = threadIdx.x;
    const int lane = tid & 31;
    const int wrp  = tid >> 5;        // 0..15
    const int f    = f0 + lane;

    // ---- prologue: load C tile ----
    #pragma unroll
    for (int idx = tid; idx < NK * 32; idx += NTHREADS)
        sC[idx] = C[(idx >> 5) * NF + f0 + (idx & 31)];
    const float bf = bias[f];
    __syncthreads();

    // ---- fold basis polys with control points (once per block) ----
    // ii = o>>5 is warp-uniform -> P reads are LDC; sC reads bank == lane.
    #pragma unroll
    for (int o = tid; o < NII * 32; o += NTHREADS) {
        const int ii = o >> 5;
        const int ln = o & 31;
        const float c0 = sC[(ii + 3) * 32 + ln];
        const float c1 = sC[(ii + 4) * 32 + ln];
        const float c2 = sC[(ii + 5) * 32 + ln];
        const float c3 = sC[(ii + 6) * 32 + ln];
        float4 q;
        q.x = T.p[ii][0][0]*c0 + T.p[ii][1][0]*c1 + T.p[ii][2][0]*c2 + T.p[ii][3][0]*c3
            + bias[f0 + ln];
        q.y = T.p[ii][0][1]*c0 + T.p[ii][1][1]*c1 + T.p[ii][2][1]*c2 + T.p[ii][3][1]*c3;
        q.z = T.p[ii][0][2]*c0 + T.p[ii][1][2]*c1 + T.p[ii][2][2]*c2 + T.p[ii][3][2]*c3;
        q.w = T.p[ii][0][3]*c0 + T.p[ii][1][3]*c1 + T.p[ii][2][3]*c2 + T.p[ii][3][3]*c3;
        sT[o] = q;
    }
    __syncthreads();
    (void)bf;

    // ---- stream batch rows: 2 rows/thread/iter for MLP, grid-stride ----
    // rows per iter per block = 32 (16 warps x 2); stride = 37*32 = 1184.
    #pragma unroll 1
    for (int b0 = bx * 32 + wrp * 2; b0 < NBATCH; b0 += NBX * 32) {
        const int  b1v = b0 + 1;
        const bool p1  = (b1v < NBATCH);
        const float x0v = X[b0 * NF + f];
        const float x1v = p1 ? X[b1v * NF + f] : 0.0f;

        const float xs0 = x0v * 55.0f;
        const float xs1 = x1v * 55.0f;
        int i0 = min((int)xs0, 54);
        int i1 = min((int)xs1, 54);
        const float u0 = xs0 - (float)i0;
        const float u1 = xs1 - (float)i1;
        // conflict-free LDS.128: ii stride = 512 B (multiple of 32 banks)
        const float4 a = sT[i0 * 32 + lane];
        const float4 c = sT[i1 * 32 + lane];
        const float r0 = fmaf(fmaf(fmaf(a.w, u0, a.z), u0, a.y), u0, a.x);
        const float r1 = fmaf(fmaf(fmaf(c.w, u1, c.z), u1, c.y), u1, c.x);
        out[b0 * NF + f] = r0;
        if (p1) out[b1v * NF + f] = r1;
    }
}

extern "C" void kernel_launch(void* const* d_in, const int* in_sizes, int n_in,
                              void* d_out, int out_size) {
    const float* x    = (const float*)d_in[0];   // (4096, 256)
    const float* ctrl = (const float*)d_in[1];   // (64, 256)
    const float* bias = (const float*)d_in[2];   // (256,)
    float* out = (float*)d_out;

    PTab T;
    make_ptab(T);   // host double math, knot-only, deterministic

    dim3 grid(NBX, NF / 32);   // (37, 8) = 296 blocks = 2/SM
    BSL_25898652795515_kernel<<<grid, NTHREADS>>>(T, x, ctrl, bias, out);
}